// round 13
// baseline (speedup 1.0000x reference)
#include <cuda_runtime.h>
#include <mma.h>
#include <cstdint>

using namespace nvcuda;

#define B_   4
#define CIN  256
#define CO   128
#define HI   64
#define WI   64
#define HO   128
#define WO   128

// Scratch buffers
__device__ float g_y[B_ * CO * HO * WO];      // deconv output (incl. bias)
__device__ float g_k[B_ * 9 * HO * WO];       // gaussian PAC weights
__device__ float g_w1a[4 * 33 * CO * 32];     // [par][chunk][o][kk], tf32
__device__ float g_w2a[37 * CO * 32];         // [chunk][o][kk], tf32; chunk36=bias

__device__ __forceinline__ float tf32r(float v) {
    float r;
    asm("cvt.rna.tf32.f32 %0, %1;" : "=f"(r) : "f"(v));
    return r;
}

// ===================== Weight prep =====================
__global__ void prep_w1a_kernel(const float* __restrict__ w1,
                                const float* __restrict__ b1) {
    int idx = blockIdx.x * blockDim.x + threadIdx.x;
    const int total = 4 * 33 * CO * 32;
    for (; idx < total; idx += gridDim.x * blockDim.x) {
        int kk    = idx & 31;
        int o     = (idx >> 5) & 127;
        int rem   = idx >> 12;          // par*33 + chunk
        int par   = rem / 33;
        int chunk = rem - par * 33;
        float v;
        if (chunk == 32) {
            v = (kk == 0) ? b1[o] : 0.f;
        } else {
            int cc = chunk >> 2, tap = chunk & 3;
            int c  = cc * 32 + kk;
            int ph = par >> 1, pw = par & 1;
            int a  = tap >> 1, bb = tap & 1;
            int kh = 2 * a + 1 - ph;
            int kw = 2 * bb + 1 - pw;
            v = w1[((c * CO + o) * 4 + kh) * 4 + kw];
        }
        g_w1a[idx] = tf32r(v);
    }
}

__global__ void prep_w2a_kernel(const float* __restrict__ w2,
                                const float* __restrict__ b2) {
    int idx = blockIdx.x * blockDim.x + threadIdx.x;
    const int total = 37 * CO * 32;
    for (; idx < total; idx += gridDim.x * blockDim.x) {
        int kk    = idx & 31;
        int o     = (idx >> 5) & 127;
        int chunk = idx >> 12;
        float v;
        if (chunk == 36) {
            v = (kk == 0) ? b2[o] : 0.f;
        } else {
            int cc = chunk / 9, tap = chunk - cc * 9;
            int c  = cc * 32 + kk;
            int i = tap / 3, j = tap - i * 3;
            v = w2[(c * CO + o) * 9 + (2 - i) * 3 + (2 - j)];
        }
        g_w2a[idx] = tf32r(v);
    }
}

// ===================== Gaussian kernel weights ==========
__global__ __launch_bounds__(256) void gauss_kernel(const float* __restrict__ guide) {
    __shared__ float gs[8 * 342];   // [c][r*19+s], pitch 19, 18 rows

    const int tid  = threadIdx.x;
    const int bimg = blockIdx.z;
    const int h0   = blockIdx.y * 16;
    const int w0   = blockIdx.x * 16;
    const int pr = tid >> 4, pc = tid & 15;

    const float* gsrc = guide + bimg * (CO * HO * WO);

    float ssd[9];
#pragma unroll
    for (int t = 0; t < 9; ++t) ssd[t] = 0.f;

    for (int c0 = 0; c0 < CO; c0 += 8) {
        for (int e = tid; e < 8 * 342; e += 256) {
            int c = e / 342;
            int rem = e - c * 342;
            int r = rem / 19, s = rem - r * 19;
            int gh = h0 - 1 + r, gw = w0 - 1 + s;
            float v = 0.f;
            if ((unsigned)gh < 128u && (unsigned)gw < 128u)
                v = gsrc[((c0 + c) * HO + gh) * WO + gw];
            gs[e] = v;
        }
        __syncthreads();
#pragma unroll
        for (int t = 0; t < 9; ++t) {
            const int ti = t / 3, tj = t - ti * 3;
            float s_ = ssd[t];
#pragma unroll
            for (int c = 0; c < 8; ++c) {
                float ctr = gs[c * 342 + (pr + 1) * 19 + (pc + 1)];
                float nb  = gs[c * 342 + (pr + ti) * 19 + (pc + tj)];
                float d = nb - ctr;
                s_ = fmaf(d, d, s_);
            }
            ssd[t] = s_;
        }
        __syncthreads();
    }
#pragma unroll
    for (int t = 0; t < 9; ++t)
        g_k[((bimg * 9 + t) * HO + h0 + pr) * WO + w0 + pc] = __expf(-0.5f * ssd[t]);
}

// ===================== WMMA fragments ==============
typedef wmma::fragment<wmma::matrix_a, 16, 16, 8, wmma::precision::tf32, wmma::row_major> FragA;
typedef wmma::fragment<wmma::matrix_b, 16, 16, 8, wmma::precision::tf32, wmma::row_major> FragB;
typedef wmma::fragment<wmma::accumulator, 16, 16, 8, float> FragC;

// smem float offsets
// halo: 32ch x 10rows x pitch19  = 6080 floats
// Bs:   2 x 32 x pitch132        = 8448 floats
// As:   2 x 128 x pitch36        = 9216 floats
// kg (pac only): 9 x 128         = 1152 floats
#define HALO_F 0
#define BS_F   6080
#define AS_F   14528
#define KG_F   23744
#define SMEM_DC_B  94976
#define SMEM_PAC_B 99584
#define CS_PITCH   132

// ===================== Stage 1: deconv via WMMA tf32, pipelined =============
__global__ __launch_bounds__(256) void deconv_wmma(const float* __restrict__ x,
                                                   const float* __restrict__ b1) {
    extern __shared__ float smf[];
    float* xs = smf + HALO_F;
    float* Bs = smf + BS_F;     // two buffers of 32*132
    float* As = smf + AS_F;     // two buffers of 128*36

    const int tid  = threadIdx.x;
    const int wid  = tid >> 5;
    const int bz   = blockIdx.z;
    const int bimg = bz >> 2;
    const int par  = bz & 3;
    const int ph = par >> 1, pw = par & 1;
    const int th0 = blockIdx.y * 8;    // parity-grid coords (0..63)
    const int tw0 = blockIdx.x * 16;

    const int warp_m = wid >> 1;       // 0..3 -> rows warp_m*32
    const int warp_n = wid & 1;        // 0..1 -> cols warp_n*64

    const int kk  = tid >> 3;          // B-build: thread owns (kk, seg)
    const int seg = tid & 7;

    const int base_h = th0 - 1 + ph;
    const int base_w = tw0 - 1 + pw;
    const float* xsrc = x + bimg * (CIN * HI * WI);
    const float* wbase = g_w1a + par * (33 * CO * 32);

    FragC cf[2][4];
#pragma unroll
    for (int i = 0; i < 2; ++i)
#pragma unroll
        for (int j = 0; j < 4; ++j) wmma::fill_fragment(cf[i][j], 0.f);

    auto buildA = [&](int chunk, int buf) {
        const float4* asrc = (const float4*)(wbase + chunk * (CO * 32));
        float* ab = As + buf * (128 * 36);
#pragma unroll
        for (int q = 0; q < 4; ++q) {
            int idx = tid + q * 256;
            int row = idx >> 3, kb = idx & 7;
            *(float4*)(ab + row * 36 + kb * 4) = __ldg(asrc + idx);
        }
    };
    auto buildB = [&](int tap, int buf) {
        const int a = tap >> 1, bb = tap & 1;
        const float* xrow = xs + kk * 190 + (seg + 1 - a) * 19 + (1 - bb);
        float* dst = Bs + buf * (32 * 132) + kk * 132 + seg * 16;
#pragma unroll
        for (int q = 0; q < 4; ++q) {
            float4 v;
            v.x = tf32r(xrow[q * 4 + 0]);
            v.y = tf32r(xrow[q * 4 + 1]);
            v.z = tf32r(xrow[q * 4 + 2]);
            v.w = tf32r(xrow[q * 4 + 3]);
            *(float4*)(dst + q * 4) = v;
        }
    };
    auto domma = [&](int buf) {
        const float* ab = As + buf * (128 * 36);
        const float* bb = Bs + buf * (32 * 132);
#pragma unroll
        for (int ks = 0; ks < 4; ++ks) {
            FragA af[2];
            FragB bf[4];
#pragma unroll
            for (int i = 0; i < 2; ++i)
                wmma::load_matrix_sync(af[i], ab + (warp_m * 32 + i * 16) * 36 + ks * 8, 36);
#pragma unroll
            for (int j = 0; j < 4; ++j)
                wmma::load_matrix_sync(bf[j], bb + ks * 8 * 132 + warp_n * 64 + j * 16, 132);
#pragma unroll
            for (int i = 0; i < 2; ++i)
#pragma unroll
                for (int j = 0; j < 4; ++j)
                    wmma::mma_sync(cf[i][j], af[i], bf[j], cf[i][j]);
        }
    };

    for (int cc = 0; cc < 8; ++cc) {
        // stage halo for 32 channels (prev builds all >=1 sync behind)
        for (int e = tid; e < 32 * 190; e += 256) {
            int c = e / 190;
            int rem = e - c * 190;
            int r = rem / 19, s = rem - r * 19;
            int ih = base_h + r, iw = base_w + s;
            float v = 0.f;
            if ((unsigned)ih < 64u && (unsigned)iw < 64u)
                v = xsrc[((cc * 32 + c) * HI + ih) * WI + iw];
            xs[e] = v;
        }
        __syncthreads();
        buildA(cc * 4, 0);
        buildB(0, 0);
        __syncthreads();
#pragma unroll
        for (int tap = 0; tap < 4; ++tap) {
            const int buf = tap & 1;
            if (tap < 3) { buildA(cc * 4 + tap + 1, buf ^ 1); buildB(tap + 1, buf ^ 1); }
            domma(buf);
            __syncthreads();
        }
    }

    // Epilogue: two passes of 64 o-rows through smem, bias + stride-2 scatter
    float* Cs = smf;   // 64 x 132, reuses halo+Bs region
#pragma unroll 1
    for (int p = 0; p < 2; ++p) {
        if ((warp_m >> 1) == p) {
#pragma unroll
            for (int i = 0; i < 2; ++i)
#pragma unroll
                for (int j = 0; j < 4; ++j)
                    wmma::store_matrix_sync(Cs + ((warp_m & 1) * 32 + i * 16) * CS_PITCH +
                                            warp_n * 64 + j * 16,
                                            cf[i][j], CS_PITCH, wmma::mem_row_major);
        }
        __syncthreads();
#pragma unroll 4
        for (int t = 0; t < 32; ++t) {
            int idx = tid + t * 256;
            int ol = idx >> 7, px = idx & 127;
            int pr = px >> 4, pc = px & 15;
            int oh = 2 * (th0 + pr) + ph;
            int ow = 2 * (tw0 + pc) + pw;
            int o  = p * 64 + ol;
            g_y[((bimg * CO + o) * HO + oh) * WO + ow] =
                Cs[ol * CS_PITCH + px] + __ldg(&b1[o]);
        }
        __syncthreads();
    }
}

// ===================== Stage 2: PAC via WMMA tf32, pipelined ================
__global__ __launch_bounds__(256) void pac_wmma(float* __restrict__ out) {
    extern __shared__ float smf[];
    float* ys = smf + HALO_F;
    float* Bs = smf + BS_F;
    float* As = smf + AS_F;
    float* kg = smf + KG_F;

    const int tid  = threadIdx.x;
    const int wid  = tid >> 5;
    const int bimg = blockIdx.z;
    const int h0   = blockIdx.y * 8;
    const int w0   = blockIdx.x * 16;

    const int warp_m = wid >> 1;
    const int warp_n = wid & 1;

    const int kk  = tid >> 3;
    const int seg = tid & 7;

    const float* ysrc = g_y + bimg * (CO * HO * WO);

    // gaussian weights for this tile: kg[t][px]
    for (int idx = tid; idx < 9 * 128; idx += 256) {
        int t = idx >> 7, px = idx & 127;
        kg[idx] = g_k[((bimg * 9 + t) * HO + h0 + (px >> 4)) * WO + w0 + (px & 15)];
    }

    FragC cf[2][4];
#pragma unroll
    for (int i = 0; i < 2; ++i)
#pragma unroll
        for (int j = 0; j < 4; ++j) wmma::fill_fragment(cf[i][j], 0.f);

    auto buildA = [&](int chunk, int buf) {
        const float4* asrc = (const float4*)(g_w2a + chunk * (CO * 32));
        float* ab = As + buf * (128 * 36);
#pragma unroll
        for (int q = 0; q < 4; ++q) {
            int idx = tid + q * 256;
            int row = idx >> 3, kb = idx & 7;
            *(float4*)(ab + row * 36 + kb * 4) = __ldg(asrc + idx);
        }
    };
    auto buildB = [&](int tap, int buf) {
        float* dst = Bs + buf * (32 * 132) + kk * 132 + seg * 16;
        if (tap == 9) {
            float v = (kk == 0) ? 1.f : 0.f;
            float4 f4 = make_float4(v, v, v, v);
#pragma unroll
            for (int q = 0; q < 4; ++q) *(float4*)(dst + q * 4) = f4;
        } else {
            const int ti = tap / 3, tj = tap - ti * 3;
            const float* yrow = ys + kk * 190 + (seg + ti) * 19 + tj;
            const float* krow = kg + tap * 128 + seg * 16;
#pragma unroll
            for (int q = 0; q < 4; ++q) {
                float4 kv = *(const float4*)(krow + q * 4);
                float4 v;
                v.x = tf32r(yrow[q * 4 + 0] * kv.x);
                v.y = tf32r(yrow[q * 4 + 1] * kv.y);
                v.z = tf32r(yrow[q * 4 + 2] * kv.z);
                v.w = tf32r(yrow[q * 4 + 3] * kv.w);
                *(float4*)(dst + q * 4) = v;
            }
        }
    };
    auto domma = [&](int buf) {
        const float* ab = As + buf * (128 * 36);
        const float* bb = Bs + buf * (32 * 132);
#pragma unroll
        for (int ks = 0; ks < 4; ++ks) {
            FragA af[2];
            FragB bf[4];
#pragma unroll
            for (int i = 0; i < 2; ++i)
                wmma::load_matrix_sync(af[i], ab + (warp_m * 32 + i * 16) * 36 + ks * 8, 36);
#pragma unroll
            for (int j = 0; j < 4; ++j)
                wmma::load_matrix_sync(bf[j], bb + ks * 8 * 132 + warp_n * 64 + j * 16, 132);
#pragma unroll
            for (int i = 0; i < 2; ++i)
#pragma unroll
                for (int j = 0; j < 4; ++j)
                    wmma::mma_sync(cf[i][j], af[i], bf[j], cf[i][j]);
        }
    };

    for (int cc = 0; cc < 4; ++cc) {
        __syncthreads();
        // stage y halo for 32 channels
        for (int e = tid; e < 32 * 190; e += 256) {
            int c = e / 190;
            int rem = e - c * 190;
            int r = rem / 19, s = rem - r * 19;
            int yh = h0 - 1 + r, yw = w0 - 1 + s;
            float v = 0.f;
            if ((unsigned)yh < 128u && (unsigned)yw < 128u)
                v = ysrc[((cc * 32 + c) * HO + yh) * WO + yw];
            ys[e] = v;
        }
        __syncthreads();
        buildA(cc * 9, 0);
        buildB(0, 0);
        __syncthreads();

        const int ntap = (cc == 3) ? 10 : 9;   // bias chunk appended to last c-block
#pragma unroll 1
        for (int tap = 0; tap < ntap; ++tap) {
            const int buf = tap & 1;
            if (tap + 1 < ntap) {
                int nchunk = (tap + 1 == 9 && cc == 3) ? 36 : cc * 9 + tap + 1;
                buildA(nchunk, buf ^ 1);
                buildB(tap + 1, buf ^ 1);
            }
            domma(buf);
            __syncthreads();
        }
    }

    // Epilogue: fragment (i,j) = o rows [warp_m*32+i*16,+16), px row warp_n*4+j
    const int m0 = warp_m * 32;
#pragma unroll
    for (int i = 0; i < 2; ++i)
#pragma unroll
        for (int j = 0; j < 4; ++j) {
            int q = warp_n * 4 + j;
            float* dst = out + ((bimg * CO + m0 + i * 16) * HO + h0 + q) * WO + w0;
            wmma::store_matrix_sync(dst, cf[i][j], HO * WO, wmma::mem_row_major);
        }
}

// ===========================================================================
extern "C" void kernel_launch(void* const* d_in, const int* in_sizes, int n_in,
                              void* d_out, int out_size) {
    const float* x     = (const float*)d_in[0];
    const float* guide = (const float*)d_in[1];
    const float* w1    = (const float*)d_in[2];
    const float* b1    = (const float*)d_in[3];
    const float* w2    = (const float*)d_in[4];
    const float* b2    = (const float*)d_in[5];
    float* out = (float*)d_out;

    static int configured = 0;
    if (!configured) {
        cudaFuncSetAttribute(deconv_wmma, cudaFuncAttributeMaxDynamicSharedMemorySize, SMEM_DC_B);
        cudaFuncSetAttribute(pac_wmma, cudaFuncAttributeMaxDynamicSharedMemorySize, SMEM_PAC_B);
        configured = 1;
    }

    prep_w1a_kernel<<<528, 256>>>(w1, b1);
    prep_w2a_kernel<<<296, 256>>>(w2, b2);
    gauss_kernel<<<dim3(8, 8, 4), 256>>>(guide);
    deconv_wmma<<<dim3(4, 8, 16), 256, SMEM_DC_B>>>(x, b1);
    pac_wmma<<<dim3(8, 16, 4), 256, SMEM_PAC_B>>>(out);
}